// round 10
// baseline (speedup 1.0000x reference)
#include <cuda_runtime.h>
#include <cuda_fp16.h>

#define NB 4
#define C  256
#define NS 4096

// ---- device scratch (allocation-free) ----
__device__ __half g_XTh[NB * NS * C];   // x^T hi  [b][q][c]
__device__ __half g_XTl[NB * NS * C];   // x^T lo
__device__ __half g_Wh[4 * C * C];      // weights hi: Wt,Wp,Wg,Wo
__device__ __half g_Wl[4 * C * C];
__device__ __half g_Th[NB * NS * C];    // theta hi [q][c]
__device__ __half g_Tl[NB * NS * C];
__device__ __half g_Ph[NB * NS * C];    // phi hi [k'][c]
__device__ __half g_Pl[NB * NS * C];
__device__ __half g_Gh[NB * C * NS];    // g fp16 [c][q]
__device__ float  g_S [(size_t)NB * NS * NS];   // logits fp32
__device__ __half g_PWh[(size_t)NB * NS * NS];  // softmax weights fp16
__device__ __half g_YTh[NB * NS * C];   // Y^T hi [q][c]
__device__ __half g_YTl[NB * NS * C];

__device__ __forceinline__ unsigned smem_u32(const void* p) {
    unsigned a;
    asm("{ .reg .u64 t; cvta.to.shared.u64 t, %1; cvt.u32.u64 %0, t; }" : "=r"(a) : "l"(p));
    return a;
}
__device__ __forceinline__ void ldsm_x4(unsigned addr, unsigned& r0, unsigned& r1,
                                        unsigned& r2, unsigned& r3) {
    asm volatile("ldmatrix.sync.aligned.m8n8.x4.shared.b16 {%0,%1,%2,%3}, [%4];"
                 : "=r"(r0), "=r"(r1), "=r"(r2), "=r"(r3) : "r"(addr));
}
__device__ __forceinline__ void mma_fp16(float* c, const unsigned* a, const unsigned* b) {
    asm volatile("mma.sync.aligned.m16n8k16.row.col.f32.f16.f16.f32 "
                 "{%0,%1,%2,%3}, {%4,%5,%6,%7}, {%8,%9}, {%0,%1,%2,%3};"
                 : "+f"(c[0]), "+f"(c[1]), "+f"(c[2]), "+f"(c[3])
                 : "r"(a[0]), "r"(a[1]), "r"(a[2]), "r"(a[3]), "r"(b[0]), "r"(b[1]));
}
__device__ __forceinline__ void cp16(unsigned dst, const void* src) {
    asm volatile("cp.async.cg.shared.global [%0], [%1], 16;" :: "r"(dst), "l"(src));
}
#define CP_COMMIT() asm volatile("cp.async.commit_group;" ::: "memory")
#define CP_WAIT(n)  asm volatile("cp.async.wait_group %0;" :: "n"(n) : "memory")

// fp16 hi/lo split of two floats, packed for half2 plane stores
__device__ __forceinline__ uint2 split2(float v0, float v1) {
    __half h0 = __float2half_rn(v0), h1 = __float2half_rn(v1);
    __half l0 = __float2half_rn(v0 - __half2float(h0));
    __half l1 = __float2half_rn(v1 - __half2float(h1));
    __half2 hh = __halves2half2(h0, h1), ll = __halves2half2(l0, l1);
    return make_uint2(*(unsigned*)&hh, *(unsigned*)&ll);
}

// tile: 128 rows x 64B (32 fp16), XOR-swizzled 16B chunks: phys = q ^ ((row>>1)&3)
#define TILE_B 8192
__device__ __forceinline__ unsigned sw_off(int row, int q16) {
    return (unsigned)(row * 64 + ((q16 ^ ((row >> 1) & 3)) << 4));
}

// ============================================================================
// Unified HMMA fp16 GEMM: D[m][n] = sum_k A[m][k] * B[n][k]  (fp32 acc)
// CFG 0: merged proj (1D grid 768): [0,512) T/P ; [512,768) G
// CFG 2: logits  A=T(2)  B=P(2)  K=C  -> fp32 g_S.  NT=4 n-tiles per CTA:
//        virtual k-loop of NT*8 chunks, pipeline never drains; inline epilogue.
// CFG 3: AV      A=PW(1) B=G(1)  K=NS -> fp16 split Y^T [q][c]
// CFG 4: out     A=Wo(2) B=YT(2) K=C  -> fp32 d_out (+bias m, +residual)
// 128x128x32 block tile, 8 warps (2x4). NST-stage cp.async, ONE barrier/chunk.
// ============================================================================
template<int CFG>
__global__ void __launch_bounds__(256, 2)
mma_k(const float* __restrict__ b1, const float* __restrict__ b2,
      const float* __restrict__ b3,
      const float* __restrict__ xres, float* __restrict__ outp)
{
    constexpr int nA = (CFG == 3) ? 1 : 2;
    constexpr int nB = (CFG == 3) ? 1 : 2;
    constexpr int PLANES = nA + nB;
    constexpr int NST = (CFG == 3) ? 4 : 3;
    constexpr int NT  = (CFG == 2) ? 4 : 1;      // n-tiles per CTA
    constexpr int STAGE_B = PLANES * TILE_B;
    const int K = (CFG == 3) ? NS : C;

    extern __shared__ unsigned su[];
    const unsigned sb = smem_u32(su);
    const int tid = threadIdx.x;
    const int wid = tid >> 5, lane = tid & 31;
    const int warp_m = wid & 1, warp_n = wid >> 1;

    const __half* Ap[2] = {nullptr, nullptr};
    const __half* Bp[2] = {nullptr, nullptr};
    int lda = C, ldb = C, batch, which = 0, m0, n0, sub = 0;

    if (CFG == 0) {
        int tile = blockIdx.x;
        if (tile < 512) {              // T/P projections
            sub = 0;
            int z = tile >> 6;
            batch = z >> 1; which = z & 1;
            int rem = tile & 63;
            m0 = (rem >> 1) * 128;
            n0 = (rem & 1) * 128;
            Ap[0] = g_XTh + (size_t)batch * NS * C;  Ap[1] = g_XTl + (size_t)batch * NS * C;
            Bp[0] = g_Wh + (size_t)which * C * C;    Bp[1] = g_Wl + (size_t)which * C * C;
        } else {                       // G projection
            sub = 1;
            int t = tile - 512;
            batch = t >> 6;
            int rem = t & 63;
            m0 = (rem >> 5) * 128;
            n0 = (rem & 31) * 128;
            Ap[0] = g_Wh + 2 * C * C;  Ap[1] = g_Wl + 2 * C * C;
            Bp[0] = g_XTh + (size_t)batch * NS * C;  Bp[1] = g_XTl + (size_t)batch * NS * C;
        }
    } else {
        batch = blockIdx.z;
        m0 = blockIdx.y * 128; n0 = blockIdx.x * (128 * NT);
        if (CFG == 2) {
            Ap[0] = g_Th + (size_t)batch * NS * C;   Ap[1] = g_Tl + (size_t)batch * NS * C;
            Bp[0] = g_Ph + (size_t)batch * NS * C;   Bp[1] = g_Pl + (size_t)batch * NS * C;
        } else if (CFG == 3) {
            Ap[0] = g_PWh + (size_t)batch * NS * NS; lda = NS;
            Bp[0] = g_Gh + (size_t)batch * C * NS;   ldb = NS;
        } else {
            Ap[0] = g_Wh + 3 * C * C;  Ap[1] = g_Wl + 3 * C * C;
            Bp[0] = g_YTh + (size_t)batch * NS * C;  Bp[1] = g_YTl + (size_t)batch * NS * C;
        }
    }

    const int nchk = K / 32;              // chunks per n-tile (8 for CFG2)
    const int tot  = nchk * NT;           // virtual chunks per CTA

    // g = virtual chunk index: tile = g / nchk, chunk-in-tile = g % nchk
    auto issue = [&](int g, int buf) {
        int t  = (NT > 1) ? (g >> 3) : 0;         // nchk==8 when NT>1
        int ch = (NT > 1) ? (g & 7) : g;
        const unsigned sbase = sb + (unsigned)buf * STAGE_B;
        const int k0 = ch * 32;
        const int nt0 = n0 + t * 128;
        #pragma unroll
        for (int c = 0; c < 2; c++) {
            int idx = tid + c * 256;
            int row = idx >> 2, q = idx & 3;
            unsigned doff = sw_off(row, q);
            #pragma unroll
            for (int p = 0; p < nA; p++)
                cp16(sbase + (unsigned)(p * TILE_B) + doff,
                     Ap[p] + (size_t)(m0 + row) * lda + k0 + q * 8);
            #pragma unroll
            for (int p = 0; p < nB; p++)
                cp16(sbase + (unsigned)((nA + p) * TILE_B) + doff,
                     Bp[p] + (size_t)(nt0 + row) * ldb + k0 + q * 8);
        }
    };

    float acc[4][4][4] = {};
    const int lrow = lane & 15;
    const int lq   = lane >> 4;
    const int erow = lane >> 2;          // epilogue row within fragment
    const int ecol = (lane & 3) * 2;

    issue(0, 0); CP_COMMIT();
    issue(1, 1); CP_COMMIT();
    if (NST == 4) { issue(2, 2); CP_COMMIT(); }

    for (int g = 0; g < tot; g++) {
        if (g >= tot - 1)                  { CP_WAIT(0); }
        else if (NST == 4 && g >= tot - 2) { CP_WAIT(1); }
        else if (NST == 4)                 { CP_WAIT(2); }
        else                               { CP_WAIT(1); }
        __syncthreads();
        if (g + NST - 1 < tot) { issue(g + NST - 1, (g + NST - 1) % NST); CP_COMMIT(); }

        const unsigned tb = sb + (unsigned)(g % NST) * STAGE_B;
        #pragma unroll
        for (int ks = 0; ks < 2; ks++) {
            const int c16 = ks * 2 + lq;
            unsigned bfr[nB][4][2];
            #pragma unroll
            for (int pb = 0; pb < nB; pb++) {
                #pragma unroll
                for (int np = 0; np < 2; np++) {
                    int brow = warp_n * 32 + np * 16 + lrow;
                    unsigned ad = tb + (unsigned)((nA + pb) * TILE_B) + sw_off(brow, c16);
                    unsigned r0, r1, r2, r3;
                    ldsm_x4(ad, r0, r1, r2, r3);
                    bfr[pb][2*np][0] = r0; bfr[pb][2*np+1][0] = r1;
                    bfr[pb][2*np][1] = r2; bfr[pb][2*np+1][1] = r3;
                }
            }
            #pragma unroll
            for (int mf = 0; mf < 4; mf++) {
                int arow = warp_m * 64 + mf * 16 + lrow;
                unsigned afr[nA][4];
                #pragma unroll
                for (int pa = 0; pa < nA; pa++) {
                    unsigned ad = tb + (unsigned)(pa * TILE_B) + sw_off(arow, c16);
                    ldsm_x4(ad, afr[pa][0], afr[pa][1], afr[pa][2], afr[pa][3]);
                }
                #pragma unroll
                for (int nf = 0; nf < 4; nf++) {
                    mma_fp16(acc[mf][nf], afr[0], bfr[0][nf]);
                    if (nA == 2 && nB == 2) {
                        mma_fp16(acc[mf][nf], afr[0], bfr[1][nf]);
                        mma_fp16(acc[mf][nf], afr[1], bfr[0][nf]);
                    }
                }
            }
        }

        // CFG2 inline per-tile epilogue: overlaps next tile's prefetch
        if (CFG == 2 && (g & 7) == 7) {
            int nt0 = n0 + (g >> 3) * 128;
            float* D = g_S + (size_t)batch * NS * NS;
            #pragma unroll
            for (int mf = 0; mf < 4; mf++) {
                int mb = m0 + warp_m * 64 + mf * 16 + erow;
                #pragma unroll
                for (int nf = 0; nf < 4; nf++) {
                    int n = nt0 + warp_n * 32 + nf * 8 + ecol;
                    float* a4 = acc[mf][nf];
                    *(float2*)&D[(size_t)mb * NS + n]       = make_float2(a4[0], a4[1]);
                    *(float2*)&D[(size_t)(mb + 8) * NS + n] = make_float2(a4[2], a4[3]);
                    a4[0] = 0.f; a4[1] = 0.f; a4[2] = 0.f; a4[3] = 0.f;
                }
            }
        }
    }

    if (CFG == 2) return;

    // ---- epilogue (non-CFG2) ----
    #pragma unroll
    for (int mf = 0; mf < 4; mf++) {
        int mb = m0 + warp_m * 64 + mf * 16 + erow;
        #pragma unroll
        for (int nf = 0; nf < 4; nf++) {
            int n = n0 + warp_n * 32 + nf * 8 + ecol;
            float* a4 = acc[mf][nf];
            if (CFG == 4) {
                float* D = outp + (size_t)batch * C * NS;
                const float* X = xres + (size_t)batch * C * NS;
                float bi0 = b1[mb], bi1 = b1[mb + 8];
                float2 x0 = *(const float2*)&X[(size_t)mb * NS + n];
                float2 x1 = *(const float2*)&X[(size_t)(mb + 8) * NS + n];
                *(float2*)&D[(size_t)mb * NS + n]       = make_float2(a4[0] + bi0 + x0.x, a4[1] + bi0 + x0.y);
                *(float2*)&D[(size_t)(mb + 8) * NS + n] = make_float2(a4[2] + bi1 + x1.x, a4[3] + bi1 + x1.y);
            } else if (CFG == 3) {   // Y^T fp16 split
                uint2 s0 = split2(a4[0], a4[1]);
                uint2 s1 = split2(a4[2], a4[3]);
                __half* Oh = g_YTh + (size_t)batch * NS * C;
                __half* Ol = g_YTl + (size_t)batch * NS * C;
                *(unsigned*)&Oh[(size_t)mb * C + n]       = s0.x;
                *(unsigned*)&Ol[(size_t)mb * C + n]       = s0.y;
                *(unsigned*)&Oh[(size_t)(mb + 8) * C + n] = s1.x;
                *(unsigned*)&Ol[(size_t)(mb + 8) * C + n] = s1.y;
            } else if (sub == 0) {   // T/P projections
                __half* Oh = (which ? g_Ph : g_Th) + (size_t)batch * NS * C;
                __half* Ol = (which ? g_Pl : g_Tl) + (size_t)batch * NS * C;
                const float* bb = which ? b2 : b1;
                float bn0 = bb[n], bn1 = bb[n + 1];
                uint2 s0 = split2(a4[0] + bn0, a4[1] + bn1);
                uint2 s1 = split2(a4[2] + bn0, a4[3] + bn1);
                *(unsigned*)&Oh[(size_t)mb * C + n]       = s0.x;
                *(unsigned*)&Ol[(size_t)mb * C + n]       = s0.y;
                *(unsigned*)&Oh[(size_t)(mb + 8) * C + n] = s1.x;
                *(unsigned*)&Ol[(size_t)(mb + 8) * C + n] = s1.y;
            } else {                 // G projection
                __half* O = g_Gh + (size_t)batch * C * NS;
                float bi0 = b3[mb], bi1 = b3[mb + 8];
                __half2 h0 = __floats2half2_rn(a4[0] + bi0, a4[1] + bi0);
                __half2 h1 = __floats2half2_rn(a4[2] + bi1, a4[3] + bi1);
                *(unsigned*)&O[(size_t)mb * NS + n]       = *(unsigned*)&h0;
                *(unsigned*)&O[(size_t)(mb + 8) * NS + n] = *(unsigned*)&h1;
            }
        }
    }
}

// ============================================================================
// x^T split: x [b][c][q] fp32 -> XTh/XTl [b][q][c] fp16. 64x64 smem tiles.
// ============================================================================
__global__ void xt_split_kernel(const float* __restrict__ x)
{
    __shared__ float tile[64][68];
    int q0 = blockIdx.x * 64, c0 = blockIdx.y * 64, b = blockIdx.z;
    int tid = threadIdx.x;
    const float* X = x + (size_t)b * C * NS;

    #pragma unroll
    for (int i = 0; i < 4; i++) {
        int c = (tid >> 4) + i * 16;
        int qq = (tid & 15) * 4;
        float4 v = *(const float4*)&X[(size_t)(c0 + c) * NS + q0 + qq];
        tile[qq + 0][c] = v.x; tile[qq + 1][c] = v.y;
        tile[qq + 2][c] = v.z; tile[qq + 3][c] = v.w;
    }
    __syncthreads();

    __half* Oh = g_XTh + (size_t)b * NS * C;
    __half* Ol = g_XTl + (size_t)b * NS * C;
    #pragma unroll
    for (int i = 0; i < 4; i++) {
        int q = (tid >> 4) + i * 16;
        int cc = (tid & 15) * 4;
        float4 v = *(const float4*)&tile[q][cc];
        uint2 s0 = split2(v.x, v.y);
        uint2 s1 = split2(v.z, v.w);
        size_t off = (size_t)(q0 + q) * C + c0 + cc;
        *(uint2*)&Oh[off] = make_uint2(s0.x, s1.x);
        *(uint2*)&Ol[off] = make_uint2(s0.y, s1.y);
    }
}

// ============================================================================
// weight split: 131072 pairs -> 512 blocks x 256 threads
// ============================================================================
__global__ void wsplit_kernel(const float* __restrict__ Wt, const float* __restrict__ Wp,
                              const float* __restrict__ Wg, const float* __restrict__ Wo)
{
    int id = blockIdx.x * 256 + threadIdx.x;
    int mat = id >> 15;
    int off = (id & 32767) * 2;
    const float* W = (mat == 0) ? Wt : (mat == 1) ? Wp : (mat == 2) ? Wg : Wo;
    float2 v = *(const float2*)&W[off];
    uint2 s = split2(v.x, v.y);
    *(unsigned*)&g_Wh[mat * C * C + off] = s.x;
    *(unsigned*)&g_Wl[mat * C * C + off] = s.y;
}

// ============================================================================
// softmax: fp32 logits -> fp16 weights
// ============================================================================
__global__ void softmax_kernel()
{
    size_t row = blockIdx.x;
    const float* p = g_S + row * (size_t)NS;
    __half* po = g_PWh + row * (size_t)NS;
    int tid = threadIdx.x;
    int lane = tid & 31, wd = tid >> 5;
    __shared__ float red[8];

    float4 v[4];
    float mx = -1e30f;
    #pragma unroll
    for (int i = 0; i < 4; i++) {
        v[i] = *(const float4*)&p[(tid + i * 256) * 4];
        mx = fmaxf(mx, fmaxf(fmaxf(v[i].x, v[i].y), fmaxf(v[i].z, v[i].w)));
    }
    #pragma unroll
    for (int off = 16; off > 0; off >>= 1)
        mx = fmaxf(mx, __shfl_xor_sync(0xffffffffu, mx, off));
    if (lane == 0) red[wd] = mx;
    __syncthreads();
    mx = red[0];
    #pragma unroll
    for (int w = 1; w < 8; w++) mx = fmaxf(mx, red[w]);

    float s = 0.f;
    #pragma unroll
    for (int i = 0; i < 4; i++) {
        v[i].x = expf(v[i].x - mx); v[i].y = expf(v[i].y - mx);
        v[i].z = expf(v[i].z - mx); v[i].w = expf(v[i].w - mx);
        s += v[i].x + v[i].y + v[i].z + v[i].w;
    }
    #pragma unroll
    for (int off = 16; off > 0; off >>= 1)
        s += __shfl_xor_sync(0xffffffffu, s, off);
    __syncthreads();
    if (lane == 0) red[wd] = s;
    __syncthreads();
    s = 0.f;
    #pragma unroll
    for (int w = 0; w < 8; w++) s += red[w];
    float inv = 1.0f / s;

    #pragma unroll
    for (int i = 0; i < 4; i++) {
        __half2 h01 = __floats2half2_rn(v[i].x * inv, v[i].y * inv);
        __half2 h23 = __floats2half2_rn(v[i].z * inv, v[i].w * inv);
        uint2 o = make_uint2(*(unsigned*)&h01, *(unsigned*)&h23);
        *(uint2*)&po[(tid + i * 256) * 4] = o;
    }
}

// ============================================================================
extern "C" void kernel_launch(void* const* d_in, const int* in_sizes, int n_in,
                              void* d_out, int out_size)
{
    const float* x  = (const float*)d_in[0];
    const float* Wg = (const float*)d_in[1];
    const float* bg = (const float*)d_in[2];
    const float* Wt = (const float*)d_in[3];
    const float* bt = (const float*)d_in[4];
    const float* Wp = (const float*)d_in[5];
    const float* bp = (const float*)d_in[6];
    const float* Wo = (const float*)d_in[7];
    const float* bo = (const float*)d_in[8];
    float* out = (float*)d_out;

    const int S4 = 3 * 4 * TILE_B;   // 98304  (3-stage, 4 planes)
    const int S2 = 4 * 2 * TILE_B;   // 65536  (4-stage, 2 planes; AV)
    cudaFuncSetAttribute(mma_k<0>, cudaFuncAttributeMaxDynamicSharedMemorySize, S4);
    cudaFuncSetAttribute(mma_k<2>, cudaFuncAttributeMaxDynamicSharedMemorySize, S4);
    cudaFuncSetAttribute(mma_k<3>, cudaFuncAttributeMaxDynamicSharedMemorySize, S2);
    cudaFuncSetAttribute(mma_k<4>, cudaFuncAttributeMaxDynamicSharedMemorySize, S4);

    wsplit_kernel  <<<512, 256>>>(Wt, Wp, Wg, Wo);
    xt_split_kernel<<<dim3(NS / 64, C / 64, NB), 256>>>(x);

    mma_k<0><<<768, 256, S4>>>(bt, bp, bg, nullptr, nullptr);                    // T,P,G
    mma_k<2><<<dim3(NS / 512, NS / 128, NB), 256, S4>>>(nullptr, nullptr, nullptr, nullptr, nullptr); // logits (4 n-tiles/CTA)
    softmax_kernel<<<NB * NS, 256>>>();
    mma_k<3><<<dim3(C / 128, NS / 128, NB), 256, S2>>>(nullptr, nullptr, nullptr, nullptr, nullptr);  // AV
    mma_k<4><<<dim3(NS / 128, C / 128, NB), 256, S4>>>(bo, nullptr, nullptr, x, out);                 // out
}

// round 11
// speedup vs baseline: 1.0239x; 1.0239x over previous
#include <cuda_runtime.h>
#include <cuda_fp16.h>

#define NB 4
#define C  256
#define NS 4096

// ---- device scratch (allocation-free) ----
__device__ __half g_XTh[NB * NS * C];   // x^T hi  [b][q][c]
__device__ __half g_XTl[NB * NS * C];   // x^T lo
__device__ __half g_Wh[4 * C * C];      // weights hi: Wt,Wp,Wg,Wo
__device__ __half g_Wl[4 * C * C];
__device__ __half g_Th[NB * NS * C];    // theta hi [q][c]
__device__ __half g_Tl[NB * NS * C];
__device__ __half g_Ph[NB * NS * C];    // phi hi [k'][c]
__device__ __half g_Pl[NB * NS * C];
__device__ __half g_Gh[NB * C * NS];    // g fp16 [c][q]
__device__ float  g_S [(size_t)NB * NS * NS];   // logits fp32
__device__ __half g_PWh[(size_t)NB * NS * NS];  // softmax weights fp16
__device__ __half g_YTh[NB * NS * C];   // Y^T hi [q][c]
__device__ __half g_YTl[NB * NS * C];

__device__ __forceinline__ unsigned smem_u32(const void* p) {
    unsigned a;
    asm("{ .reg .u64 t; cvta.to.shared.u64 t, %1; cvt.u32.u64 %0, t; }" : "=r"(a) : "l"(p));
    return a;
}
__device__ __forceinline__ void ldsm_x4(unsigned addr, unsigned& r0, unsigned& r1,
                                        unsigned& r2, unsigned& r3) {
    asm volatile("ldmatrix.sync.aligned.m8n8.x4.shared.b16 {%0,%1,%2,%3}, [%4];"
                 : "=r"(r0), "=r"(r1), "=r"(r2), "=r"(r3) : "r"(addr));
}
__device__ __forceinline__ void mma_fp16(float* c, const unsigned* a, const unsigned* b) {
    asm volatile("mma.sync.aligned.m16n8k16.row.col.f32.f16.f16.f32 "
                 "{%0,%1,%2,%3}, {%4,%5,%6,%7}, {%8,%9}, {%0,%1,%2,%3};"
                 : "+f"(c[0]), "+f"(c[1]), "+f"(c[2]), "+f"(c[3])
                 : "r"(a[0]), "r"(a[1]), "r"(a[2]), "r"(a[3]), "r"(b[0]), "r"(b[1]));
}
__device__ __forceinline__ void cp16(unsigned dst, const void* src) {
    asm volatile("cp.async.cg.shared.global [%0], [%1], 16;" :: "r"(dst), "l"(src));
}
#define CP_COMMIT() asm volatile("cp.async.commit_group;" ::: "memory")
#define CP_WAIT(n)  asm volatile("cp.async.wait_group %0;" :: "n"(n) : "memory")

// fp16 hi/lo split of two floats, packed for half2 plane stores
__device__ __forceinline__ uint2 split2(float v0, float v1) {
    __half h0 = __float2half_rn(v0), h1 = __float2half_rn(v1);
    __half l0 = __float2half_rn(v0 - __half2float(h0));
    __half l1 = __float2half_rn(v1 - __half2float(h1));
    __half2 hh = __halves2half2(h0, h1), ll = __halves2half2(l0, l1);
    return make_uint2(*(unsigned*)&hh, *(unsigned*)&ll);
}

// tile: 128 rows x 64B (32 fp16), XOR-swizzled 16B chunks: phys = q ^ ((row>>1)&3)
#define TILE_B 8192
__device__ __forceinline__ unsigned sw_off(int row, int q16) {
    return (unsigned)(row * 64 + ((q16 ^ ((row >> 1) & 3)) << 4));
}

// ============================================================================
// Unified HMMA fp16 GEMM: D[m][n] = sum_k A[m][k] * B[n][k]  (fp32 acc)
// CFG 0: merged proj (1D grid 768): [0,512) T/P ; [512,768) G
// CFG 2: logits  A=T(2)  B=P(2)  K=C  -> fp32 g_S
// CFG 3: AV      A=PW(1) B=G(1)  K=NS -> fp16 split Y^T [q][c]
// CFG 4: out     A=Wo(2) B=YT(2) K=C  -> fp32 d_out (+bias m, +residual)
// 128x128x32 block tile, 8 warps (2x4). NST-stage cp.async, ONE barrier/chunk.
// 3-term mma order: per mf, term-outer / nf-inner -> same-acc reuse distance 4.
// ============================================================================
template<int CFG>
__global__ void __launch_bounds__(256, 2)
mma_k(const float* __restrict__ b1, const float* __restrict__ b2,
      const float* __restrict__ b3,
      const float* __restrict__ xres, float* __restrict__ outp)
{
    constexpr int nA = (CFG == 3) ? 1 : 2;
    constexpr int nB = (CFG == 3) ? 1 : 2;
    constexpr int PLANES = nA + nB;
    constexpr int NST = (CFG == 3) ? 4 : 3;
    constexpr int STAGE_B = PLANES * TILE_B;
    const int K = (CFG == 3) ? NS : C;

    extern __shared__ unsigned su[];
    const unsigned sb = smem_u32(su);
    const int tid = threadIdx.x;
    const int wid = tid >> 5, lane = tid & 31;
    const int warp_m = wid & 1, warp_n = wid >> 1;

    const __half* Ap[2] = {nullptr, nullptr};
    const __half* Bp[2] = {nullptr, nullptr};
    int lda = C, ldb = C, batch, which = 0, m0, n0, sub = 0;

    if (CFG == 0) {
        int tile = blockIdx.x;
        if (tile < 512) {              // T/P projections
            sub = 0;
            int z = tile >> 6;
            batch = z >> 1; which = z & 1;
            int rem = tile & 63;
            m0 = (rem >> 1) * 128;
            n0 = (rem & 1) * 128;
            Ap[0] = g_XTh + (size_t)batch * NS * C;  Ap[1] = g_XTl + (size_t)batch * NS * C;
            Bp[0] = g_Wh + (size_t)which * C * C;    Bp[1] = g_Wl + (size_t)which * C * C;
        } else {                       // G projection
            sub = 1;
            int t = tile - 512;
            batch = t >> 6;
            int rem = t & 63;
            m0 = (rem >> 5) * 128;
            n0 = (rem & 31) * 128;
            Ap[0] = g_Wh + 2 * C * C;  Ap[1] = g_Wl + 2 * C * C;
            Bp[0] = g_XTh + (size_t)batch * NS * C;  Bp[1] = g_XTl + (size_t)batch * NS * C;
        }
    } else {
        batch = blockIdx.z;
        m0 = blockIdx.y * 128; n0 = blockIdx.x * 128;
        if (CFG == 2) {
            Ap[0] = g_Th + (size_t)batch * NS * C;   Ap[1] = g_Tl + (size_t)batch * NS * C;
            Bp[0] = g_Ph + (size_t)batch * NS * C;   Bp[1] = g_Pl + (size_t)batch * NS * C;
        } else if (CFG == 3) {
            Ap[0] = g_PWh + (size_t)batch * NS * NS; lda = NS;
            Bp[0] = g_Gh + (size_t)batch * C * NS;   ldb = NS;
        } else {
            Ap[0] = g_Wh + 3 * C * C;  Ap[1] = g_Wl + 3 * C * C;
            Bp[0] = g_YTh + (size_t)batch * NS * C;  Bp[1] = g_YTl + (size_t)batch * NS * C;
        }
    }

    auto issue = [&](int chunk, int buf) {
        const unsigned sbase = sb + (unsigned)buf * STAGE_B;
        const int k0 = chunk * 32;
        #pragma unroll
        for (int c = 0; c < 2; c++) {
            int idx = tid + c * 256;
            int row = idx >> 2, q = idx & 3;
            unsigned doff = sw_off(row, q);
            #pragma unroll
            for (int p = 0; p < nA; p++)
                cp16(sbase + (unsigned)(p * TILE_B) + doff,
                     Ap[p] + (size_t)(m0 + row) * lda + k0 + q * 8);
            #pragma unroll
            for (int p = 0; p < nB; p++)
                cp16(sbase + (unsigned)((nA + p) * TILE_B) + doff,
                     Bp[p] + (size_t)(n0 + row) * ldb + k0 + q * 8);
        }
    };

    float acc[4][4][4] = {};
    const int lrow = lane & 15;
    const int lq   = lane >> 4;
    const int nch = K / 32;

    issue(0, 0); CP_COMMIT();
    issue(1, 1); CP_COMMIT();
    if (NST == 4) { issue(2, 2); CP_COMMIT(); }

    for (int i = 0; i < nch; i++) {
        if (i >= nch - 1)                  { CP_WAIT(0); }
        else if (NST == 4 && i >= nch - 2) { CP_WAIT(1); }
        else if (NST == 4)                 { CP_WAIT(2); }
        else                               { CP_WAIT(1); }
        __syncthreads();
        if (i + NST - 1 < nch) { issue(i + NST - 1, (i + NST - 1) % NST); CP_COMMIT(); }

        const unsigned tb = sb + (unsigned)(i % NST) * STAGE_B;
        #pragma unroll
        for (int ks = 0; ks < 2; ks++) {
            const int c16 = ks * 2 + lq;
            unsigned bfr[nB][4][2];
            #pragma unroll
            for (int pb = 0; pb < nB; pb++) {
                #pragma unroll
                for (int np = 0; np < 2; np++) {
                    int brow = warp_n * 32 + np * 16 + lrow;
                    unsigned ad = tb + (unsigned)((nA + pb) * TILE_B) + sw_off(brow, c16);
                    unsigned r0, r1, r2, r3;
                    ldsm_x4(ad, r0, r1, r2, r3);
                    bfr[pb][2*np][0] = r0; bfr[pb][2*np+1][0] = r1;
                    bfr[pb][2*np][1] = r2; bfr[pb][2*np+1][1] = r3;
                }
            }
            #pragma unroll
            for (int mf = 0; mf < 4; mf++) {
                int arow = warp_m * 64 + mf * 16 + lrow;
                unsigned afr[nA][4];
                #pragma unroll
                for (int pa = 0; pa < nA; pa++) {
                    unsigned ad = tb + (unsigned)(pa * TILE_B) + sw_off(arow, c16);
                    ldsm_x4(ad, afr[pa][0], afr[pa][1], afr[pa][2], afr[pa][3]);
                }
                if (nA == 2 && nB == 2) {
                    // term-outer / nf-inner: same-acc reuse distance = 4
                    #pragma unroll
                    for (int nf = 0; nf < 4; nf++) mma_fp16(acc[mf][nf], afr[0], bfr[0][nf]);
                    #pragma unroll
                    for (int nf = 0; nf < 4; nf++) mma_fp16(acc[mf][nf], afr[0], bfr[1][nf]);
                    #pragma unroll
                    for (int nf = 0; nf < 4; nf++) mma_fp16(acc[mf][nf], afr[1], bfr[0][nf]);
                } else {
                    #pragma unroll
                    for (int nf = 0; nf < 4; nf++) mma_fp16(acc[mf][nf], afr[0], bfr[0][nf]);
                }
            }
        }
    }

    // ---- epilogue ----
    #pragma unroll
    for (int mf = 0; mf < 4; mf++) {
        int mb = m0 + warp_m * 64 + mf * 16 + (lane >> 2);
        #pragma unroll
        for (int nf = 0; nf < 4; nf++) {
            int n = n0 + warp_n * 32 + nf * 8 + (lane & 3) * 2;
            float* a4 = acc[mf][nf];
            if (CFG == 2) {
                float* D = g_S + (size_t)batch * NS * NS;
                *(float2*)&D[(size_t)mb * NS + n]       = make_float2(a4[0], a4[1]);
                *(float2*)&D[(size_t)(mb + 8) * NS + n] = make_float2(a4[2], a4[3]);
            } else if (CFG == 4) {
                float* D = outp + (size_t)batch * C * NS;
                const float* X = xres + (size_t)batch * C * NS;
                float bi0 = b1[mb], bi1 = b1[mb + 8];
                float2 x0 = *(const float2*)&X[(size_t)mb * NS + n];
                float2 x1 = *(const float2*)&X[(size_t)(mb + 8) * NS + n];
                *(float2*)&D[(size_t)mb * NS + n]       = make_float2(a4[0] + bi0 + x0.x, a4[1] + bi0 + x0.y);
                *(float2*)&D[(size_t)(mb + 8) * NS + n] = make_float2(a4[2] + bi1 + x1.x, a4[3] + bi1 + x1.y);
            } else if (CFG == 3) {   // Y^T fp16 split
                uint2 s0 = split2(a4[0], a4[1]);
                uint2 s1 = split2(a4[2], a4[3]);
                __half* Oh = g_YTh + (size_t)batch * NS * C;
                __half* Ol = g_YTl + (size_t)batch * NS * C;
                *(unsigned*)&Oh[(size_t)mb * C + n]       = s0.x;
                *(unsigned*)&Ol[(size_t)mb * C + n]       = s0.y;
                *(unsigned*)&Oh[(size_t)(mb + 8) * C + n] = s1.x;
                *(unsigned*)&Ol[(size_t)(mb + 8) * C + n] = s1.y;
            } else if (sub == 0) {   // T/P projections
                __half* Oh = (which ? g_Ph : g_Th) + (size_t)batch * NS * C;
                __half* Ol = (which ? g_Pl : g_Tl) + (size_t)batch * NS * C;
                const float* bb = which ? b2 : b1;
                float bn0 = bb[n], bn1 = bb[n + 1];
                uint2 s0 = split2(a4[0] + bn0, a4[1] + bn1);
                uint2 s1 = split2(a4[2] + bn0, a4[3] + bn1);
                *(unsigned*)&Oh[(size_t)mb * C + n]       = s0.x;
                *(unsigned*)&Ol[(size_t)mb * C + n]       = s0.y;
                *(unsigned*)&Oh[(size_t)(mb + 8) * C + n] = s1.x;
                *(unsigned*)&Ol[(size_t)(mb + 8) * C + n] = s1.y;
            } else {                 // G projection
                __half* O = g_Gh + (size_t)batch * C * NS;
                float bi0 = b3[mb], bi1 = b3[mb + 8];
                __half2 h0 = __floats2half2_rn(a4[0] + bi0, a4[1] + bi0);
                __half2 h1 = __floats2half2_rn(a4[2] + bi1, a4[3] + bi1);
                *(unsigned*)&O[(size_t)mb * NS + n]       = *(unsigned*)&h0;
                *(unsigned*)&O[(size_t)(mb + 8) * NS + n] = *(unsigned*)&h1;
            }
        }
    }
}

// ============================================================================
// x^T split: x [b][c][q] fp32 -> XTh/XTl [b][q][c] fp16. 64x64 smem tiles.
// ============================================================================
__global__ void xt_split_kernel(const float* __restrict__ x)
{
    __shared__ float tile[64][68];
    int q0 = blockIdx.x * 64, c0 = blockIdx.y * 64, b = blockIdx.z;
    int tid = threadIdx.x;
    const float* X = x + (size_t)b * C * NS;

    #pragma unroll
    for (int i = 0; i < 4; i++) {
        int c = (tid >> 4) + i * 16;
        int qq = (tid & 15) * 4;
        float4 v = *(const float4*)&X[(size_t)(c0 + c) * NS + q0 + qq];
        tile[qq + 0][c] = v.x; tile[qq + 1][c] = v.y;
        tile[qq + 2][c] = v.z; tile[qq + 3][c] = v.w;
    }
    __syncthreads();

    __half* Oh = g_XTh + (size_t)b * NS * C;
    __half* Ol = g_XTl + (size_t)b * NS * C;
    #pragma unroll
    for (int i = 0; i < 4; i++) {
        int q = (tid >> 4) + i * 16;
        int cc = (tid & 15) * 4;
        float4 v = *(const float4*)&tile[q][cc];
        uint2 s0 = split2(v.x, v.y);
        uint2 s1 = split2(v.z, v.w);
        size_t off = (size_t)(q0 + q) * C + c0 + cc;
        *(uint2*)&Oh[off] = make_uint2(s0.x, s1.x);
        *(uint2*)&Ol[off] = make_uint2(s0.y, s1.y);
    }
}

// ============================================================================
// weight split: 131072 pairs -> 512 blocks x 256 threads
// ============================================================================
__global__ void wsplit_kernel(const float* __restrict__ Wt, const float* __restrict__ Wp,
                              const float* __restrict__ Wg, const float* __restrict__ Wo)
{
    int id = blockIdx.x * 256 + threadIdx.x;
    int mat = id >> 15;
    int off = (id & 32767) * 2;
    const float* W = (mat == 0) ? Wt : (mat == 1) ? Wp : (mat == 2) ? Wg : Wo;
    float2 v = *(const float2*)&W[off];
    uint2 s = split2(v.x, v.y);
    *(unsigned*)&g_Wh[mat * C * C + off] = s.x;
    *(unsigned*)&g_Wl[mat * C * C + off] = s.y;
}

// ============================================================================
// softmax: fp32 logits -> fp16 weights
// ============================================================================
__global__ void softmax_kernel()
{
    size_t row = blockIdx.x;
    const float* p = g_S + row * (size_t)NS;
    __half* po = g_PWh + row * (size_t)NS;
    int tid = threadIdx.x;
    int lane = tid & 31, wd = tid >> 5;
    __shared__ float red[8];

    float4 v[4];
    float mx = -1e30f;
    #pragma unroll
    for (int i = 0; i < 4; i++) {
        v[i] = *(const float4*)&p[(tid + i * 256) * 4];
        mx = fmaxf(mx, fmaxf(fmaxf(v[i].x, v[i].y), fmaxf(v[i].z, v[i].w)));
    }
    #pragma unroll
    for (int off = 16; off > 0; off >>= 1)
        mx = fmaxf(mx, __shfl_xor_sync(0xffffffffu, mx, off));
    if (lane == 0) red[wd] = mx;
    __syncthreads();
    mx = red[0];
    #pragma unroll
    for (int w = 1; w < 8; w++) mx = fmaxf(mx, red[w]);

    float s = 0.f;
    #pragma unroll
    for (int i = 0; i < 4; i++) {
        v[i].x = expf(v[i].x - mx); v[i].y = expf(v[i].y - mx);
        v[i].z = expf(v[i].z - mx); v[i].w = expf(v[i].w - mx);
        s += v[i].x + v[i].y + v[i].z + v[i].w;
    }
    #pragma unroll
    for (int off = 16; off > 0; off >>= 1)
        s += __shfl_xor_sync(0xffffffffu, s, off);
    __syncthreads();
    if (lane == 0) red[wd] = s;
    __syncthreads();
    s = 0.f;
    #pragma unroll
    for (int w = 0; w < 8; w++) s += red[w];
    float inv = 1.0f / s;

    #pragma unroll
    for (int i = 0; i < 4; i++) {
        __half2 h01 = __floats2half2_rn(v[i].x * inv, v[i].y * inv);
        __half2 h23 = __floats2half2_rn(v[i].z * inv, v[i].w * inv);
        uint2 o = make_uint2(*(unsigned*)&h01, *(unsigned*)&h23);
        *(uint2*)&po[(tid + i * 256) * 4] = o;
    }
}

// ============================================================================
extern "C" void kernel_launch(void* const* d_in, const int* in_sizes, int n_in,
                              void* d_out, int out_size)
{
    const float* x  = (const float*)d_in[0];
    const float* Wg = (const float*)d_in[1];
    const float* bg = (const float*)d_in[2];
    const float* Wt = (const float*)d_in[3];
    const float* bt = (const float*)d_in[4];
    const float* Wp = (const float*)d_in[5];
    const float* bp = (const float*)d_in[6];
    const float* Wo = (const float*)d_in[7];
    const float* bo = (const float*)d_in[8];
    float* out = (float*)d_out;

    const int S4 = 3 * 4 * TILE_B;   // 98304  (3-stage, 4 planes)
    const int S2 = 4 * 2 * TILE_B;   // 65536  (4-stage, 2 planes; AV)
    cudaFuncSetAttribute(mma_k<0>, cudaFuncAttributeMaxDynamicSharedMemorySize, S4);
    cudaFuncSetAttribute(mma_k<2>, cudaFuncAttributeMaxDynamicSharedMemorySize, S4);
    cudaFuncSetAttribute(mma_k<3>, cudaFuncAttributeMaxDynamicSharedMemorySize, S2);
    cudaFuncSetAttribute(mma_k<4>, cudaFuncAttributeMaxDynamicSharedMemorySize, S4);

    wsplit_kernel  <<<512, 256>>>(Wt, Wp, Wg, Wo);
    xt_split_kernel<<<dim3(NS / 64, C / 64, NB), 256>>>(x);

    mma_k<0><<<768, 256, S4>>>(bt, bp, bg, nullptr, nullptr);                    // T,P,G
    mma_k<2><<<dim3(NS / 128, NS / 128, NB), 256, S4>>>(nullptr, nullptr, nullptr, nullptr, nullptr); // logits
    softmax_kernel<<<NB * NS, 256>>>();
    mma_k<3><<<dim3(C / 128, NS / 128, NB), 256, S2>>>(nullptr, nullptr, nullptr, nullptr, nullptr);  // AV
    mma_k<4><<<dim3(NS / 128, C / 128, NB), 256, S4>>>(bo, nullptr, nullptr, x, out);                 // out
}

// round 12
// speedup vs baseline: 1.0490x; 1.0245x over previous
#include <cuda_runtime.h>
#include <cuda_fp16.h>

#define NB 4
#define C  256
#define NS 4096

// ---- device scratch (allocation-free) ----
__device__ __half g_XTh[NB * NS * C];   // x^T hi  [b][q][c]
__device__ __half g_XTl[NB * NS * C];   // x^T lo
__device__ __half g_Wh[4 * C * C];      // weights hi: Wt,Wp,Wg,Wo
__device__ __half g_Wl[4 * C * C];
__device__ __half g_Th[NB * NS * C];    // theta hi [q][c]
__device__ __half g_Tl[NB * NS * C];
__device__ __half g_Ph[NB * NS * C];    // phi hi [k'][c]
__device__ __half g_Pl[NB * NS * C];
__device__ __half g_Gh[NB * C * NS];    // g fp16 [c][q]
__device__ float  g_S [(size_t)NB * NS * NS];   // logits fp32
__device__ __half g_PWh[(size_t)NB * NS * NS];  // softmax weights fp16
__device__ __half g_YTh[NB * NS * C];   // Y^T hi [q][c]
__device__ __half g_YTl[NB * NS * C];

__device__ __forceinline__ unsigned smem_u32(const void* p) {
    unsigned a;
    asm("{ .reg .u64 t; cvta.to.shared.u64 t, %1; cvt.u32.u64 %0, t; }" : "=r"(a) : "l"(p));
    return a;
}
__device__ __forceinline__ void ldsm_x4(unsigned addr, unsigned& r0, unsigned& r1,
                                        unsigned& r2, unsigned& r3) {
    asm volatile("ldmatrix.sync.aligned.m8n8.x4.shared.b16 {%0,%1,%2,%3}, [%4];"
                 : "=r"(r0), "=r"(r1), "=r"(r2), "=r"(r3) : "r"(addr));
}
__device__ __forceinline__ void mma_fp16(float* c, const unsigned* a, const unsigned* b) {
    asm volatile("mma.sync.aligned.m16n8k16.row.col.f32.f16.f16.f32 "
                 "{%0,%1,%2,%3}, {%4,%5,%6,%7}, {%8,%9}, {%0,%1,%2,%3};"
                 : "+f"(c[0]), "+f"(c[1]), "+f"(c[2]), "+f"(c[3])
                 : "r"(a[0]), "r"(a[1]), "r"(a[2]), "r"(a[3]), "r"(b[0]), "r"(b[1]));
}
__device__ __forceinline__ void cp16(unsigned dst, const void* src) {
    asm volatile("cp.async.cg.shared.global [%0], [%1], 16;" :: "r"(dst), "l"(src));
}
#define CP_COMMIT() asm volatile("cp.async.commit_group;" ::: "memory")
#define CP_WAIT(n)  asm volatile("cp.async.wait_group %0;" :: "n"(n) : "memory")

// fp16 hi/lo split of two floats, packed for half2 plane stores
__device__ __forceinline__ uint2 split2(float v0, float v1) {
    __half h0 = __float2half_rn(v0), h1 = __float2half_rn(v1);
    __half l0 = __float2half_rn(v0 - __half2float(h0));
    __half l1 = __float2half_rn(v1 - __half2float(h1));
    __half2 hh = __halves2half2(h0, h1), ll = __halves2half2(l0, l1);
    return make_uint2(*(unsigned*)&hh, *(unsigned*)&ll);
}

// tile row: 64B (32 fp16), XOR-swizzled 16B chunks: phys = q ^ ((row>>1)&3)
#define TILE_B 8192
__device__ __forceinline__ unsigned sw_off(int row, int q16) {
    return (unsigned)(row * 64 + ((q16 ^ ((row >> 1) & 3)) << 4));
}

// ============================================================================
// logits kernel: D[q][k'] = sum_c T[q][c]*P[k'][c], 3-term fp16 split.
// Block tile 128x64x32, 8 warps (4x2), warp tile 32x32, acc=32 regs/thread.
// 3 CTAs/SM (24 warps) via launch_bounds(256,3), 3-stage cp.async.
// smem stage: Ah(8K) Al(8K) Bh(4K) Bl(4K) = 24KB; 3 stages = 72KB.
// ============================================================================
#define L_STAGE 24576
__global__ void __launch_bounds__(256, 3)
logits_kernel()
{
    extern __shared__ unsigned su[];
    const unsigned sb = smem_u32(su);
    const int tid = threadIdx.x;
    const int wid = tid >> 5, lane = tid & 31;
    const int warp_m = wid & 3, warp_n = wid >> 2;   // 4 x 2
    const int m0 = blockIdx.y * 128, n0 = blockIdx.x * 64;
    const int batch = blockIdx.z;

    const __half* Ah = g_Th + (size_t)batch * NS * C;
    const __half* Al = g_Tl + (size_t)batch * NS * C;
    const __half* Bh = g_Ph + (size_t)batch * NS * C;
    const __half* Bl = g_Pl + (size_t)batch * NS * C;
    float* D = g_S + (size_t)batch * NS * NS;

    auto issue = [&](int chunk, int buf) {
        const unsigned sbase = sb + (unsigned)buf * L_STAGE;
        const int k0 = chunk * 32;
        #pragma unroll
        for (int c = 0; c < 2; c++) {            // A: 128 rows
            int idx = tid + c * 256;
            int row = idx >> 2, q = idx & 3;
            unsigned doff = sw_off(row, q);
            cp16(sbase + doff,        Ah + (size_t)(m0 + row) * C + k0 + q * 8);
            cp16(sbase + 8192 + doff, Al + (size_t)(m0 + row) * C + k0 + q * 8);
        }
        {                                         // B: 64 rows
            int row = tid >> 2, q = tid & 3;
            unsigned doff = sw_off(row, q);
            cp16(sbase + 16384 + doff, Bh + (size_t)(n0 + row) * C + k0 + q * 8);
            cp16(sbase + 20480 + doff, Bl + (size_t)(n0 + row) * C + k0 + q * 8);
        }
    };

    float acc[2][4][4] = {};
    const int lrow = lane & 15;
    const int lq   = lane >> 4;
    const int nch = C / 32;    // 8

    issue(0, 0); CP_COMMIT();
    issue(1, 1); CP_COMMIT();

    for (int i = 0; i < nch; i++) {
        if (i >= nch - 1) { CP_WAIT(0); } else { CP_WAIT(1); }
        __syncthreads();
        if (i + 2 < nch) { issue(i + 2, (i + 2) % 3); CP_COMMIT(); }

        const unsigned tb = sb + (unsigned)(i % 3) * L_STAGE;
        #pragma unroll
        for (int ks = 0; ks < 2; ks++) {
            const int c16 = ks * 2 + lq;
            unsigned bfr[2][4][2];
            #pragma unroll
            for (int pb = 0; pb < 2; pb++) {
                #pragma unroll
                for (int np = 0; np < 2; np++) {
                    int brow = warp_n * 32 + np * 16 + lrow;
                    unsigned ad = tb + (unsigned)(16384 + pb * 4096) + sw_off(brow, c16);
                    unsigned r0, r1, r2, r3;
                    ldsm_x4(ad, r0, r1, r2, r3);
                    bfr[pb][2*np][0] = r0; bfr[pb][2*np+1][0] = r1;
                    bfr[pb][2*np][1] = r2; bfr[pb][2*np+1][1] = r3;
                }
            }
            #pragma unroll
            for (int mf = 0; mf < 2; mf++) {
                int arow = warp_m * 32 + mf * 16 + lrow;
                unsigned ah4[4], al4[4];
                ldsm_x4(tb + sw_off(arow, c16), ah4[0], ah4[1], ah4[2], ah4[3]);
                ldsm_x4(tb + 8192 + sw_off(arow, c16), al4[0], al4[1], al4[2], al4[3]);
                #pragma unroll
                for (int nf = 0; nf < 4; nf++) {
                    mma_fp16(acc[mf][nf], ah4, bfr[0][nf]);
                    mma_fp16(acc[mf][nf], ah4, bfr[1][nf]);
                    mma_fp16(acc[mf][nf], al4, bfr[0][nf]);
                }
            }
        }
    }

    #pragma unroll
    for (int mf = 0; mf < 2; mf++) {
        int mb = m0 + warp_m * 32 + mf * 16 + (lane >> 2);
        #pragma unroll
        for (int nf = 0; nf < 4; nf++) {
            int n = n0 + warp_n * 32 + nf * 8 + (lane & 3) * 2;
            float* a4 = acc[mf][nf];
            *(float2*)&D[(size_t)mb * NS + n]       = make_float2(a4[0], a4[1]);
            *(float2*)&D[(size_t)(mb + 8) * NS + n] = make_float2(a4[2], a4[3]);
        }
    }
}

// ============================================================================
// Unified HMMA fp16 GEMM (proj / AV / out) — round-9 proven structure.
// CFG 0: merged proj (1D grid 768): [0,512) T/P ; [512,768) G
// CFG 3: AV      A=PW(1) B=G(1)  K=NS -> fp16 split Y^T [q][c]
// CFG 4: out     A=Wo(2) B=YT(2) K=C  -> fp32 d_out (+bias m, +residual)
// ============================================================================
template<int CFG>
__global__ void __launch_bounds__(256, 2)
mma_k(const float* __restrict__ b1, const float* __restrict__ b2,
      const float* __restrict__ b3,
      const float* __restrict__ xres, float* __restrict__ outp)
{
    constexpr int nA = (CFG == 3) ? 1 : 2;
    constexpr int nB = (CFG == 3) ? 1 : 2;
    constexpr int NST = (CFG == 3) ? 4 : 3;
    constexpr int STAGE_B = (nA + nB) * TILE_B;
    const int K = (CFG == 3) ? NS : C;

    extern __shared__ unsigned su[];
    const unsigned sb = smem_u32(su);
    const int tid = threadIdx.x;
    const int wid = tid >> 5, lane = tid & 31;
    const int warp_m = wid & 1, warp_n = wid >> 1;

    const __half* Ap[2] = {nullptr, nullptr};
    const __half* Bp[2] = {nullptr, nullptr};
    int lda = C, ldb = C, batch, which = 0, m0, n0, sub = 0;

    if (CFG == 0) {
        int tile = blockIdx.x;
        if (tile < 512) {
            sub = 0;
            int z = tile >> 6;
            batch = z >> 1; which = z & 1;
            int rem = tile & 63;
            m0 = (rem >> 1) * 128;
            n0 = (rem & 1) * 128;
            Ap[0] = g_XTh + (size_t)batch * NS * C;  Ap[1] = g_XTl + (size_t)batch * NS * C;
            Bp[0] = g_Wh + (size_t)which * C * C;    Bp[1] = g_Wl + (size_t)which * C * C;
        } else {
            sub = 1;
            int t = tile - 512;
            batch = t >> 6;
            int rem = t & 63;
            m0 = (rem >> 5) * 128;
            n0 = (rem & 31) * 128;
            Ap[0] = g_Wh + 2 * C * C;  Ap[1] = g_Wl + 2 * C * C;
            Bp[0] = g_XTh + (size_t)batch * NS * C;  Bp[1] = g_XTl + (size_t)batch * NS * C;
        }
    } else {
        batch = blockIdx.z;
        m0 = blockIdx.y * 128; n0 = blockIdx.x * 128;
        if (CFG == 3) {
            Ap[0] = g_PWh + (size_t)batch * NS * NS; lda = NS;
            Bp[0] = g_Gh + (size_t)batch * C * NS;   ldb = NS;
        } else {
            Ap[0] = g_Wh + 3 * C * C;  Ap[1] = g_Wl + 3 * C * C;
            Bp[0] = g_YTh + (size_t)batch * NS * C;  Bp[1] = g_YTl + (size_t)batch * NS * C;
        }
    }

    auto issue = [&](int chunk, int buf) {
        const unsigned sbase = sb + (unsigned)buf * STAGE_B;
        const int k0 = chunk * 32;
        #pragma unroll
        for (int c = 0; c < 2; c++) {
            int idx = tid + c * 256;
            int row = idx >> 2, q = idx & 3;
            unsigned doff = sw_off(row, q);
            #pragma unroll
            for (int p = 0; p < nA; p++)
                cp16(sbase + (unsigned)(p * TILE_B) + doff,
                     Ap[p] + (size_t)(m0 + row) * lda + k0 + q * 8);
            #pragma unroll
            for (int p = 0; p < nB; p++)
                cp16(sbase + (unsigned)((nA + p) * TILE_B) + doff,
                     Bp[p] + (size_t)(n0 + row) * ldb + k0 + q * 8);
        }
    };

    float acc[4][4][4] = {};
    const int lrow = lane & 15;
    const int lq   = lane >> 4;
    const int nch = K / 32;

    issue(0, 0); CP_COMMIT();
    issue(1, 1); CP_COMMIT();
    if (NST == 4) { issue(2, 2); CP_COMMIT(); }

    for (int i = 0; i < nch; i++) {
        if (i >= nch - 1)                  { CP_WAIT(0); }
        else if (NST == 4 && i >= nch - 2) { CP_WAIT(1); }
        else if (NST == 4)                 { CP_WAIT(2); }
        else                               { CP_WAIT(1); }
        __syncthreads();
        if (i + NST - 1 < nch) { issue(i + NST - 1, (i + NST - 1) % NST); CP_COMMIT(); }

        const unsigned tb = sb + (unsigned)(i % NST) * STAGE_B;
        #pragma unroll
        for (int ks = 0; ks < 2; ks++) {
            const int c16 = ks * 2 + lq;
            unsigned bfr[nB][4][2];
            #pragma unroll
            for (int pb = 0; pb < nB; pb++) {
                #pragma unroll
                for (int np = 0; np < 2; np++) {
                    int brow = warp_n * 32 + np * 16 + lrow;
                    unsigned ad = tb + (unsigned)((nA + pb) * TILE_B) + sw_off(brow, c16);
                    unsigned r0, r1, r2, r3;
                    ldsm_x4(ad, r0, r1, r2, r3);
                    bfr[pb][2*np][0] = r0; bfr[pb][2*np+1][0] = r1;
                    bfr[pb][2*np][1] = r2; bfr[pb][2*np+1][1] = r3;
                }
            }
            #pragma unroll
            for (int mf = 0; mf < 4; mf++) {
                int arow = warp_m * 64 + mf * 16 + lrow;
                unsigned afr[nA][4];
                #pragma unroll
                for (int pa = 0; pa < nA; pa++) {
                    unsigned ad = tb + (unsigned)(pa * TILE_B) + sw_off(arow, c16);
                    ldsm_x4(ad, afr[pa][0], afr[pa][1], afr[pa][2], afr[pa][3]);
                }
                if (nA == 2 && nB == 2) {
                    #pragma unroll
                    for (int nf = 0; nf < 4; nf++) mma_fp16(acc[mf][nf], afr[0], bfr[0][nf]);
                    #pragma unroll
                    for (int nf = 0; nf < 4; nf++) mma_fp16(acc[mf][nf], afr[0], bfr[1][nf]);
                    #pragma unroll
                    for (int nf = 0; nf < 4; nf++) mma_fp16(acc[mf][nf], afr[1], bfr[0][nf]);
                } else {
                    #pragma unroll
                    for (int nf = 0; nf < 4; nf++) mma_fp16(acc[mf][nf], afr[0], bfr[0][nf]);
                }
            }
        }
    }

    // ---- epilogue ----
    #pragma unroll
    for (int mf = 0; mf < 4; mf++) {
        int mb = m0 + warp_m * 64 + mf * 16 + (lane >> 2);
        #pragma unroll
        for (int nf = 0; nf < 4; nf++) {
            int n = n0 + warp_n * 32 + nf * 8 + (lane & 3) * 2;
            float* a4 = acc[mf][nf];
            if (CFG == 4) {
                float* D = outp + (size_t)batch * C * NS;
                const float* X = xres + (size_t)batch * C * NS;
                float bi0 = b1[mb], bi1 = b1[mb + 8];
                float2 x0 = *(const float2*)&X[(size_t)mb * NS + n];
                float2 x1 = *(const float2*)&X[(size_t)(mb + 8) * NS + n];
                *(float2*)&D[(size_t)mb * NS + n]       = make_float2(a4[0] + bi0 + x0.x, a4[1] + bi0 + x0.y);
                *(float2*)&D[(size_t)(mb + 8) * NS + n] = make_float2(a4[2] + bi1 + x1.x, a4[3] + bi1 + x1.y);
            } else if (CFG == 3) {
                uint2 s0 = split2(a4[0], a4[1]);
                uint2 s1 = split2(a4[2], a4[3]);
                __half* Oh = g_YTh + (size_t)batch * NS * C;
                __half* Ol = g_YTl + (size_t)batch * NS * C;
                *(unsigned*)&Oh[(size_t)mb * C + n]       = s0.x;
                *(unsigned*)&Ol[(size_t)mb * C + n]       = s0.y;
                *(unsigned*)&Oh[(size_t)(mb + 8) * C + n] = s1.x;
                *(unsigned*)&Ol[(size_t)(mb + 8) * C + n] = s1.y;
            } else if (sub == 0) {
                __half* Oh = (which ? g_Ph : g_Th) + (size_t)batch * NS * C;
                __half* Ol = (which ? g_Pl : g_Tl) + (size_t)batch * NS * C;
                const float* bb = which ? b2 : b1;
                float bn0 = bb[n], bn1 = bb[n + 1];
                uint2 s0 = split2(a4[0] + bn0, a4[1] + bn1);
                uint2 s1 = split2(a4[2] + bn0, a4[3] + bn1);
                *(unsigned*)&Oh[(size_t)mb * C + n]       = s0.x;
                *(unsigned*)&Ol[(size_t)mb * C + n]       = s0.y;
                *(unsigned*)&Oh[(size_t)(mb + 8) * C + n] = s1.x;
                *(unsigned*)&Ol[(size_t)(mb + 8) * C + n] = s1.y;
            } else {
                __half* O = g_Gh + (size_t)batch * C * NS;
                float bi0 = b3[mb], bi1 = b3[mb + 8];
                __half2 h0 = __floats2half2_rn(a4[0] + bi0, a4[1] + bi0);
                __half2 h1 = __floats2half2_rn(a4[2] + bi1, a4[3] + bi1);
                *(unsigned*)&O[(size_t)mb * NS + n]       = *(unsigned*)&h0;
                *(unsigned*)&O[(size_t)(mb + 8) * NS + n] = *(unsigned*)&h1;
            }
        }
    }
}

// ============================================================================
// x^T split: x [b][c][q] fp32 -> XTh/XTl [b][q][c] fp16. 64x64 smem tiles.
// ============================================================================
__global__ void xt_split_kernel(const float* __restrict__ x)
{
    __shared__ float tile[64][68];
    int q0 = blockIdx.x * 64, c0 = blockIdx.y * 64, b = blockIdx.z;
    int tid = threadIdx.x;
    const float* X = x + (size_t)b * C * NS;

    #pragma unroll
    for (int i = 0; i < 4; i++) {
        int c = (tid >> 4) + i * 16;
        int qq = (tid & 15) * 4;
        float4 v = *(const float4*)&X[(size_t)(c0 + c) * NS + q0 + qq];
        tile[qq + 0][c] = v.x; tile[qq + 1][c] = v.y;
        tile[qq + 2][c] = v.z; tile[qq + 3][c] = v.w;
    }
    __syncthreads();

    __half* Oh = g_XTh + (size_t)b * NS * C;
    __half* Ol = g_XTl + (size_t)b * NS * C;
    #pragma unroll
    for (int i = 0; i < 4; i++) {
        int q = (tid >> 4) + i * 16;
        int cc = (tid & 15) * 4;
        float4 v = *(const float4*)&tile[q][cc];
        uint2 s0 = split2(v.x, v.y);
        uint2 s1 = split2(v.z, v.w);
        size_t off = (size_t)(q0 + q) * C + c0 + cc;
        *(uint2*)&Oh[off] = make_uint2(s0.x, s1.x);
        *(uint2*)&Ol[off] = make_uint2(s0.y, s1.y);
    }
}

// ============================================================================
// weight split: 131072 pairs -> 512 blocks x 256 threads
// ============================================================================
__global__ void wsplit_kernel(const float* __restrict__ Wt, const float* __restrict__ Wp,
                              const float* __restrict__ Wg, const float* __restrict__ Wo)
{
    int id = blockIdx.x * 256 + threadIdx.x;
    int mat = id >> 15;
    int off = (id & 32767) * 2;
    const float* W = (mat == 0) ? Wt : (mat == 1) ? Wp : (mat == 2) ? Wg : Wo;
    float2 v = *(const float2*)&W[off];
    uint2 s = split2(v.x, v.y);
    *(unsigned*)&g_Wh[mat * C * C + off] = s.x;
    *(unsigned*)&g_Wl[mat * C * C + off] = s.y;
}

// ============================================================================
// softmax: fp32 logits -> fp16 weights
// ============================================================================
__global__ void softmax_kernel()
{
    size_t row = blockIdx.x;
    const float* p = g_S + row * (size_t)NS;
    __half* po = g_PWh + row * (size_t)NS;
    int tid = threadIdx.x;
    int lane = tid & 31, wd = tid >> 5;
    __shared__ float red[8];

    float4 v[4];
    float mx = -1e30f;
    #pragma unroll
    for (int i = 0; i < 4; i++) {
        v[i] = *(const float4*)&p[(tid + i * 256) * 4];
        mx = fmaxf(mx, fmaxf(fmaxf(v[i].x, v[i].y), fmaxf(v[i].z, v[i].w)));
    }
    #pragma unroll
    for (int off = 16; off > 0; off >>= 1)
        mx = fmaxf(mx, __shfl_xor_sync(0xffffffffu, mx, off));
    if (lane == 0) red[wd] = mx;
    __syncthreads();
    mx = red[0];
    #pragma unroll
    for (int w = 1; w < 8; w++) mx = fmaxf(mx, red[w]);

    float s = 0.f;
    #pragma unroll
    for (int i = 0; i < 4; i++) {
        v[i].x = expf(v[i].x - mx); v[i].y = expf(v[i].y - mx);
        v[i].z = expf(v[i].z - mx); v[i].w = expf(v[i].w - mx);
        s += v[i].x + v[i].y + v[i].z + v[i].w;
    }
    #pragma unroll
    for (int off = 16; off > 0; off >>= 1)
        s += __shfl_xor_sync(0xffffffffu, s, off);
    __syncthreads();
    if (lane == 0) red[wd] = s;
    __syncthreads();
    s = 0.f;
    #pragma unroll
    for (int w = 0; w < 8; w++) s += red[w];
    float inv = 1.0f / s;

    #pragma unroll
    for (int i = 0; i < 4; i++) {
        __half2 h01 = __floats2half2_rn(v[i].x * inv, v[i].y * inv);
        __half2 h23 = __floats2half2_rn(v[i].z * inv, v[i].w * inv);
        uint2 o = make_uint2(*(unsigned*)&h01, *(unsigned*)&h23);
        *(uint2*)&po[(tid + i * 256) * 4] = o;
    }
}

// ============================================================================
extern "C" void kernel_launch(void* const* d_in, const int* in_sizes, int n_in,
                              void* d_out, int out_size)
{
    const float* x  = (const float*)d_in[0];
    const float* Wg = (const float*)d_in[1];
    const float* bg = (const float*)d_in[2];
    const float* Wt = (const float*)d_in[3];
    const float* bt = (const float*)d_in[4];
    const float* Wp = (const float*)d_in[5];
    const float* bp = (const float*)d_in[6];
    const float* Wo = (const float*)d_in[7];
    const float* bo = (const float*)d_in[8];
    float* out = (float*)d_out;

    const int S4 = 3 * 4 * TILE_B;   // 98304 (proj/out)
    const int S2 = 4 * 2 * TILE_B;   // 65536 (AV)
    const int SL = 3 * L_STAGE;      // 73728 (logits)
    cudaFuncSetAttribute(mma_k<0>, cudaFuncAttributeMaxDynamicSharedMemorySize, S4);
    cudaFuncSetAttribute(logits_kernel, cudaFuncAttributeMaxDynamicSharedMemorySize, SL);
    cudaFuncSetAttribute(mma_k<3>, cudaFuncAttributeMaxDynamicSharedMemorySize, S2);
    cudaFuncSetAttribute(mma_k<4>, cudaFuncAttributeMaxDynamicSharedMemorySize, S4);

    wsplit_kernel  <<<512, 256>>>(Wt, Wp, Wg, Wo);
    xt_split_kernel<<<dim3(NS / 64, C / 64, NB), 256>>>(x);

    mma_k<0><<<768, 256, S4>>>(bt, bp, bg, nullptr, nullptr);                    // T,P,G
    logits_kernel<<<dim3(NS / 64, NS / 128, NB), 256, SL>>>();                   // logits
    softmax_kernel<<<NB * NS, 256>>>();
    mma_k<3><<<dim3(C / 128, NS / 128, NB), 256, S2>>>(nullptr, nullptr, nullptr, nullptr, nullptr);  // AV
    mma_k<4><<<dim3(NS / 128, C / 128, NB), 256, S4>>>(bo, nullptr, nullptr, x, out);                 // out
}